// round 14
// baseline (speedup 1.0000x reference)
#include <cuda_runtime.h>
#include <cuda_fp16.h>
#include <math.h>
#include <cstdint>

// DirectAU loss: align + uniformity on N=8192, D=64 fp32 vectors.
//   align   = mean_i ||u_hat_i - i_hat_i||^2
//   uniform = (log(2*S_u/(N(N-1)) + eps) + log(2*S_i/(N(N-1)) + eps)) / 2
//   where S = sum_{i>j} exp(-2 * max(2 - 2 <x_i, x_j>, 0))
//
// R9: k_pair double-buffers its smem tiles (dynamic, 73.8 KB) so that
//  (a) next tile's cp.async is in flight across the whole mainloop+epilogue
//  (b) no barrier sits between the HMMA mainloop and the EX2 epilogue ->
//      tensor and MUFU pipes overlap instead of serializing
//  (c) epilogue uses a 4-way split accumulator to break the FADD chain.

#define NROWS  8192
#define DDIM   64
#define TILE   128
#define NTILES 64
#define NPAIRS 2080            // NTILES*(NTILES+1)/2
#define NWORK  (2 * NPAIRS)
#define EPS_U  1e-8f
#define GRID_PAIR 304          // 2 CTAs per SM (152 SMs on GB300)

// dynamic smem layout (bytes): two buffers of (A tile + B tile), then red[]
#define S_PITCH 144            // 72 halfs per row
#define S_AB    18432          // 128 * 144
#define S_BUF   36864          // A + B
#define S_RED   73728
#define S_TOT   (S_RED + 64)

__device__ float g_align[NROWS];
__device__ float g_S[NWORK];
__device__ unsigned int g_h16[2][NROWS * 32];   // fp16x2-packed normalized rows

// ---------------------------------------------------------------------------
// PTX helpers
// ---------------------------------------------------------------------------
__device__ __forceinline__ uint32_t smem_u32(const void* p) {
    uint32_t a;
    asm("{ .reg .u64 t; cvta.to.shared.u64 t, %1; cvt.u32.u64 %0, t; }"
        : "=r"(a) : "l"(p));
    return a;
}
__device__ __forceinline__ void ldsm4(uint32_t* r, uint32_t addr) {
    asm volatile("ldmatrix.sync.aligned.m8n8.x4.shared.b16 {%0,%1,%2,%3}, [%4];"
                 : "=r"(r[0]), "=r"(r[1]), "=r"(r[2]), "=r"(r[3]) : "r"(addr));
}
__device__ __forceinline__ void mma16816(float* d, const uint32_t* a,
                                         uint32_t b0, uint32_t b1) {
    asm volatile("mma.sync.aligned.m16n8k16.row.col.f32.f16.f16.f32 "
                 "{%0,%1,%2,%3},{%4,%5,%6,%7},{%8,%9},{%0,%1,%2,%3};"
                 : "+f"(d[0]), "+f"(d[1]), "+f"(d[2]), "+f"(d[3])
                 : "r"(a[0]), "r"(a[1]), "r"(a[2]), "r"(a[3]), "r"(b0), "r"(b1));
}
__device__ __forceinline__ void cp16(uint32_t saddr, const void* g) {
    asm volatile("cp.async.cg.shared.global [%0], [%1], 16;"
                 :: "r"(saddr), "l"(g) : "memory");
}
__device__ __forceinline__ float ex2f(float z) {
    float e;
    asm("ex2.approx.ftz.f32 %0, %1;" : "=f"(e) : "f"(z));
    return e;
}

// ---------------------------------------------------------------------------
// Kernel 1: normalize both matrices, per-row alignment, fp16 pack.
// ---------------------------------------------------------------------------
__global__ void __launch_bounds__(256) k_norm_align(const float* __restrict__ U,
                                                    const float* __restrict__ I)
{
    int warp = threadIdx.x >> 5;
    int lane = threadIdx.x & 31;
    int row  = blockIdx.x * 8 + warp;

    float2 u = ((const float2*)U)[row * 32 + lane];
    float2 v = ((const float2*)I)[row * 32 + lane];

    float su = u.x * u.x + u.y * u.y;
    float sv = v.x * v.x + v.y * v.y;
    #pragma unroll
    for (int o = 16; o > 0; o >>= 1) {
        su += __shfl_xor_sync(0xffffffffu, su, o);
        sv += __shfl_xor_sync(0xffffffffu, sv, o);
    }
    float ru = rsqrtf(su); ru = ru * (1.5f - 0.5f * su * ru * ru);
    float rv = rsqrtf(sv); rv = rv * (1.5f - 0.5f * sv * rv * rv);

    float2 un = make_float2(u.x * ru, u.y * ru);
    float2 vn = make_float2(v.x * rv, v.y * rv);

    __half2 uh = __float22half2_rn(un);
    __half2 vh = __float22half2_rn(vn);
    int idx = row * 32 + lane;
    g_h16[0][idx] = *reinterpret_cast<unsigned int*>(&uh);
    g_h16[1][idx] = *reinterpret_cast<unsigned int*>(&vh);

    float dx = un.x - vn.x, dy = un.y - vn.y;
    float a = dx * dx + dy * dy;
    #pragma unroll
    for (int o = 16; o > 0; o >>= 1)
        a += __shfl_xor_sync(0xffffffffu, a, o);
    if (lane == 0) g_align[row] = a;
}

// ---------------------------------------------------------------------------
// Kernel 2: persistent, double-buffered Gram tile-pair worker.
// ---------------------------------------------------------------------------
__device__ __forceinline__ void decode_work(int w, int& mat, int& ibase,
                                            int& jbase, bool& diag)
{
    mat = (w >= NPAIRS) ? 1 : 0;
    int t = w - mat * NPAIRS;
    int bi = (int)((sqrtf(8.0f * (float)t + 1.0f) - 1.0f) * 0.5f);
    while ((bi + 1) * (bi + 2) / 2 <= t) ++bi;
    while (bi * (bi + 1) / 2 > t) --bi;
    int bj = t - bi * (bi + 1) / 2;
    diag  = (bi == bj);
    ibase = bi * TILE;
    jbase = bj * TILE;
}

__global__ void __launch_bounds__(256, 2) k_pair()
{
    extern __shared__ __align__(16) char smem[];
    const uint32_t sb = smem_u32(smem);
    float* red = (float*)(smem + S_RED);

    const int tid  = threadIdx.x;
    const int wid  = tid >> 5;
    const int lane = tid & 31;

    // per-thread load slots: 4 x (row, chunk); cp.async 16B each per tile
    int l_row[4], l_ch[4];
    uint32_t l_off[4];                       // offset within a tile buffer
    #pragma unroll
    for (int r = 0; r < 4; ++r) {
        int idx  = tid + 256 * r;
        l_row[r] = idx >> 3;
        l_ch[r]  = idx & 7;
        l_off[r] = (uint32_t)(l_row[r] * S_PITCH + l_ch[r] * 16);
    }

    const int wm = wid & 1;
    const int wn = wid >> 1;
    const int m0 = wm * 64;
    const int n0 = wn * 32;
    const uint32_t a_off = (uint32_t)((lane & 15) * S_PITCH + ((lane >> 4) * 8) * 2);
    const uint32_t b_off = (uint32_t)(((((lane >> 4) & 1) * 8 + (lane & 7)) * S_PITCH)
                                      + (((lane >> 3) & 1) * 8) * 2);

    int w = blockIdx.x;
    int mat, ibase, jbase; bool diag;
    int buf = 0;

    if (w < NWORK) {
        decode_work(w, mat, ibase, jbase, diag);
        const uint4* src = (const uint4*)g_h16[mat];
        const uint32_t ab = sb;            // buf 0 A
        const uint32_t bb = sb + S_AB;     // buf 0 B
        #pragma unroll
        for (int r = 0; r < 4; ++r) {
            cp16(ab + l_off[r], &src[(ibase + l_row[r]) * 8 + l_ch[r]]);
            cp16(bb + l_off[r], &src[(jbase + l_row[r]) * 8 + l_ch[r]]);
        }
        asm volatile("cp.async.commit_group;" ::: "memory");
    }

    while (w < NWORK) {
        // issue next tile into the other buffer (its last readers synced at
        // the end of the previous iteration)
        const int w_next = w + gridDim.x;
        int nmat, nib, njb; bool ndiag;
        if (w_next < NWORK) {
            decode_work(w_next, nmat, nib, njb, ndiag);
            const uint4* src = (const uint4*)g_h16[nmat];
            const uint32_t ab = sb + (buf ^ 1) * S_BUF;
            const uint32_t bb = ab + S_AB;
            #pragma unroll
            for (int r = 0; r < 4; ++r) {
                cp16(ab + l_off[r], &src[(nib + l_row[r]) * 8 + l_ch[r]]);
                cp16(bb + l_off[r], &src[(njb + l_row[r]) * 8 + l_ch[r]]);
            }
            asm volatile("cp.async.commit_group;" ::: "memory");
            asm volatile("cp.async.wait_group 1;" ::: "memory");
        } else {
            asm volatile("cp.async.wait_group 0;" ::: "memory");
        }
        __syncthreads();   // current buffer fully written, all warps aligned

        const uint32_t abase = sb + buf * S_BUF;
        const uint32_t bbase = abase + S_AB;

        // mainloop: 4 k-steps of 16, ldmatrix + mma.sync fp16
        float acc[4][4][4];
        #pragma unroll
        for (int mf = 0; mf < 4; ++mf)
            #pragma unroll
            for (int nf = 0; nf < 4; ++nf)
                #pragma unroll
                for (int r = 0; r < 4; ++r) acc[mf][nf][r] = 0.0f;

        #pragma unroll
        for (int ks = 0; ks < 4; ++ks) {
            const uint32_t k0b = (uint32_t)(ks * 16 * 2);
            uint32_t A[4][4];
            #pragma unroll
            for (int mf = 0; mf < 4; ++mf)
                ldsm4(A[mf], abase + (uint32_t)((m0 + mf * 16) * S_PITCH) + k0b + a_off);
            uint32_t B[2][4];
            #pragma unroll
            for (int nb = 0; nb < 2; ++nb)
                ldsm4(B[nb], bbase + (uint32_t)((n0 + nb * 16) * S_PITCH) + k0b + b_off);
            #pragma unroll
            for (int mf = 0; mf < 4; ++mf)
                #pragma unroll
                for (int nf = 0; nf < 4; ++nf)
                    mma16816(acc[mf][nf], A[mf],
                             B[nf >> 1][(nf & 1) * 2], B[nf >> 1][(nf & 1) * 2 + 1]);
        }

        // epilogue (NO barrier before this: ptxas interleaves EX2 with the
        // tail of the HMMA chains). term = ex2(d*K2 - K2), K2 = 4*log2(e).
        const float K2 = 5.7707801635558535f;
        float s0 = 0.0f, s1 = 0.0f, s2 = 0.0f, s3 = 0.0f;
        if (!diag) {
            #pragma unroll
            for (int mf = 0; mf < 4; ++mf)
                #pragma unroll
                for (int nf = 0; nf < 4; ++nf) {
                    const float* d = acc[mf][nf];
                    s0 += ex2f(fmaf(d[0], K2, -K2));
                    s1 += ex2f(fmaf(d[1], K2, -K2));
                    s2 += ex2f(fmaf(d[2], K2, -K2));
                    s3 += ex2f(fmaf(d[3], K2, -K2));
                }
        } else {
            #pragma unroll
            for (int mf = 0; mf < 4; ++mf) {
                const int gi0 = ibase + m0 + mf * 16 + (lane >> 2);
                #pragma unroll
                for (int nf = 0; nf < 4; ++nf) {
                    const int gj0 = jbase + n0 + nf * 8 + (lane & 3) * 2;
                    const float* d = acc[mf][nf];
                    #pragma unroll
                    for (int r = 0; r < 4; ++r) {
                        int gi = gi0 + ((r >> 1) << 3);
                        int gj = gj0 + (r & 1);
                        float term = ex2f(fminf(d[r], 1.0f) * K2 - K2);
                        if (gj < gi) s0 += term;
                    }
                }
            }
        }
        float s = (s0 + s1) + (s2 + s3);

        // warp shfl-reduce, then cross-warp pass. The syncthreads here also
        // guards the current buffer against the next iteration's cp.async.
        #pragma unroll
        for (int o = 16; o > 0; o >>= 1)
            s += __shfl_xor_sync(0xffffffffu, s, o);
        if (lane == 0) red[wid] = s;
        __syncthreads();
        if (tid == 0) {
            float tot = 0.0f;
            #pragma unroll
            for (int i = 0; i < 8; ++i) tot += red[i];
            g_S[w] = tot;
        }

        w = w_next;
        mat = nmat; ibase = nib; jbase = njb; diag = ndiag;
        buf ^= 1;
    }
}

// ---------------------------------------------------------------------------
// Kernel 3: deterministic final reduction + scalar assembly.
// ---------------------------------------------------------------------------
__device__ __forceinline__ float block_sum(const float* src, int n,
                                           float* red, int tid)
{
    float a = 0.0f;
    for (int i = tid; i < n; i += 256) a += src[i];
    red[tid] = a;
    __syncthreads();
    #pragma unroll
    for (int o = 128; o > 0; o >>= 1) {
        if (tid < o) red[tid] += red[tid + o];
        __syncthreads();
    }
    float r = red[0];
    __syncthreads();
    return r;
}

__global__ void k_final(float* __restrict__ out)
{
    __shared__ float red[256];
    int tid = threadIdx.x;

    float align_sum = block_sum(g_align, NROWS, red, tid);
    float su        = block_sum(g_S, NPAIRS, red, tid);
    float si        = block_sum(g_S + NPAIRS, NPAIRS, red, tid);

    if (tid == 0) {
        const float denom = (float)NROWS * (float)(NROWS - 1);
        float align  = align_sum / (float)NROWS;
        float log_u  = logf(2.0f * su / denom + EPS_U);
        float log_i  = logf(2.0f * si / denom + EPS_U);
        out[0] = align + 0.5f * (log_u + log_i);   // GAMMA = 1
    }
}

extern "C" void kernel_launch(void* const* d_in, const int* in_sizes, int n_in,
                              void* d_out, int out_size)
{
    const float* U = (const float*)d_in[0];
    const float* I = (const float*)d_in[1];
    float* out = (float*)d_out;

    cudaFuncSetAttribute(k_pair, cudaFuncAttributeMaxDynamicSharedMemorySize,
                         S_TOT);

    k_norm_align<<<NROWS / 8, 256>>>(U, I);
    k_pair<<<GRID_PAIR, 256, S_TOT>>>();
    k_final<<<1, 256>>>(out);
}